// round 9
// baseline (speedup 1.0000x reference)
#include <cuda_runtime.h>

// Shapes fixed by the problem: L=512, B=64, H=1024.
#define HDIM 1024
#define LDIM 512
#define BDIM 64
#define KSPLIT 64
#define KPER (HDIM / KSPLIT)   // 16

// Scratch (device globals — no allocation allowed anywhere).
__device__ float g_wpart[KSPLIT * HDIM];
__device__ float g_w[HDIM];
__device__ float g_s[BDIM * LDIM];

// ---------------------------------------------------------------------------
// k0: partial w[h] = sum over a k-chunk of W_att[k, H + h] * v[k].
// grid (1, KSPLIT) x 256 threads; each thread owns 4 consecutive h (float4).
// 16 back-to-back LDG.128.CS per thread (W_att read exactly once).
// 64 CTAs spread across 64 SMs -> ~64KB of the 4MB slab each.
// ---------------------------------------------------------------------------
__global__ void __launch_bounds__(256) wpart_kernel(const float* __restrict__ W_att,
                                                    const float* __restrict__ vec) {
    const int h4 = threadIdx.x;                      // float4 index, 0..255
    const int kc = blockIdx.y;                       // k-chunk
    const float4* base =
        reinterpret_cast<const float4*>(W_att + (size_t)kc * KPER * (2 * HDIM) + HDIM) + h4;
    const float* vbase = vec + kc * KPER;
    float4 acc = make_float4(0.f, 0.f, 0.f, 0.f);
#pragma unroll
    for (int k = 0; k < KPER; ++k) {
        const float4 r = __ldcs(base + (size_t)k * (2 * HDIM / 4));
        const float  v = __ldg(vbase + k);
        acc.x += r.x * v; acc.y += r.y * v; acc.z += r.z * v; acc.w += r.w * v;
    }
    reinterpret_cast<float4*>(g_wpart + kc * HDIM)[h4] = acc;
}

// ---------------------------------------------------------------------------
// k1: w[h] = sum_j g_wpart[j][h].  1 block x 256 threads, float4 per thread.
// Data is L2-resident (just written); wide loads + full unroll.
// ---------------------------------------------------------------------------
__global__ void __launch_bounds__(256) wreduce_kernel() {
    const int h4 = threadIdx.x;                      // float4 index, 0..255
    float4 acc = make_float4(0.f, 0.f, 0.f, 0.f);
#pragma unroll
    for (int j = 0; j < KSPLIT; ++j) {
        const float4 r = reinterpret_cast<const float4*>(g_wpart + j * HDIM)[h4];
        acc.x += r.x; acc.y += r.y; acc.z += r.z; acc.w += r.w;
    }
    reinterpret_cast<float4*>(g_w)[h4] = acc;
}

// ---------------------------------------------------------------------------
// k2: the HBM-bound streaming dot (dominant launch, ~128 MB read).
// One warp per (l,b) row: 1024 floats = 8 float4 per lane.
// All 8 LDG.E.128.CS issued back-to-back (front-batched MLP=8; __ldcs since
// the stream has zero reuse), THEN w is read from smem inside the FMA loop.
// __launch_bounds__(256, 4) pins the reg budget (<=64/thread) so 4 CTAs
// (32 warps) co-reside per SM: 32KB in-flight loads per SM ~ 2x the
// latency-hiding requirement for ~8 TB/s at 577-cyc DRAM latency.
// Stores transposed s[b, l] so softmax reads are coalesced.
// grid 4096 x 256 threads (8 warps).
// ---------------------------------------------------------------------------
__global__ void __launch_bounds__(256, 4) dot_kernel(const float* __restrict__ hs) {
    __shared__ float4 ws4[HDIM / 4];
    const int tid = threadIdx.x;
    if (tid < HDIM / 4) ws4[tid] = reinterpret_cast<const float4*>(g_w)[tid];
    __syncthreads();

    const int warp = tid >> 5;
    const int lane = tid & 31;
    const int row  = blockIdx.x * 8 + warp;           // row = l*64 + b, 0..32767

    const float4* p = reinterpret_cast<const float4*>(hs + (size_t)row * HDIM);
    float4 a[8];
#pragma unroll
    for (int i = 0; i < 8; ++i) a[i] = __ldcs(p + lane + 32 * i);

    float acc = 0.f;
#pragma unroll
    for (int i = 0; i < 8; ++i) {
        const float4 w = ws4[lane + 32 * i];          // conflict-free LDS.128
        acc += a[i].x * w.x + a[i].y * w.y + a[i].z * w.z + a[i].w * w.w;
    }

#pragma unroll
    for (int off = 16; off; off >>= 1)
        acc += __shfl_xor_sync(0xffffffffu, acc, off);

    if (lane == 0) {
        const int l = row >> 6;     // / 64
        const int b = row & 63;     // % 64
        g_s[b * LDIM + l] = acc;
    }
}

// ---------------------------------------------------------------------------
// k3: softmax over l per b. grid 64 x 512 threads (one thread per l).
// ---------------------------------------------------------------------------
__global__ void __launch_bounds__(512) softmax_kernel(float* __restrict__ out) {
    __shared__ float red[16];
    const int b    = blockIdx.x;
    const int t    = threadIdx.x;
    const int warp = t >> 5;
    const int lane = t & 31;

    const float x = g_s[b * LDIM + t];

    // block max
    float m = x;
#pragma unroll
    for (int off = 16; off; off >>= 1)
        m = fmaxf(m, __shfl_xor_sync(0xffffffffu, m, off));
    if (lane == 0) red[warp] = m;
    __syncthreads();
    float M = red[0];
#pragma unroll
    for (int j = 1; j < 16; ++j) M = fmaxf(M, red[j]);
    __syncthreads();  // before reusing red[]

    const float e = expf(x - M);

    // block sum
    float s = e;
#pragma unroll
    for (int off = 16; off; off >>= 1)
        s += __shfl_xor_sync(0xffffffffu, s, off);
    if (lane == 0) red[warp] = s;
    __syncthreads();
    float S = red[0];
#pragma unroll
    for (int j = 1; j < 16; ++j) S += red[j];

    out[b * LDIM + t] = e / S;   // out shape (B, 1, L)
}

// ---------------------------------------------------------------------------
// Launch. Expected metadata order: hidden(0), hs_encoder(1), W_att(2),
// b_att(3), vector(4). hidden / Wh / b_att cancel under softmax
// shift-invariance (per-b constant added to every logit along l).
// hs_encoder and W_att are resolved by their unique element counts;
// vector = LAST input with H elements (b_att precedes vector in the dict).
// ---------------------------------------------------------------------------
extern "C" void kernel_launch(void* const* d_in, const int* in_sizes, int n_in,
                              void* d_out, int out_size) {
    const float* hs  = (const float*)d_in[1];
    const float* W   = (const float*)d_in[2];
    const float* vec = (const float*)d_in[4];
    for (int i = 0; i < n_in; ++i) {
        if (in_sizes[i] == LDIM * BDIM * HDIM) hs = (const float*)d_in[i];
        else if (in_sizes[i] == HDIM * 2 * HDIM) W = (const float*)d_in[i];
        else if (in_sizes[i] == HDIM) vec = (const float*)d_in[i];  // last H-sized wins
    }
    float* out = (float*)d_out;

    wpart_kernel<<<dim3(1, KSPLIT), 256>>>(W, vec);
    wreduce_kernel<<<1, 256>>>();
    dot_kernel<<<(LDIM * BDIM) / 8, 256>>>(hs);
    softmax_kernel<<<BDIM, 512>>>(out);
}